// round 1
// baseline (speedup 1.0000x reference)
#include <cuda_runtime.h>
#include <math.h>

#define HC 128
#define NVMAX 50000
#define NEMAX 400000
#define NG 512
#define LAYERS 2

// ---------------- scratch (device globals; no allocation) ----------------
__device__ float g_xs0[NVMAX * HC];
__device__ float g_xs1[NVMAX * HC];
__device__ float g_tmp[NVMAX * HC];
__device__ float g_kt[NVMAX * HC];
__device__ float g_vt[NVMAX * HC];
__device__ float g_q[NVMAX * HC];
__device__ float g_aggv[NVMAX * HC];
__device__ float g_aggc[NVMAX * HC];
__device__ float g_alpha[NEMAX * 4];
__device__ float g_amax[NVMAX * 4];
__device__ float g_den[NVMAX * 4];
__device__ float g_wea[HC * HC];
__device__ float g_wem[HC * HC];
__device__ float g_gsum[NG * 2];
__device__ float g_gcnt[NG];

// ---------------- small utility kernels ----------------
__global__ void fill_kernel(float* __restrict__ p, float v, int n) {
    int i = blockIdx.x * blockDim.x + threadIdx.x;
    if (i < n) p[i] = v;
}

// expand [H,D,D] relation tensor into dense block-diagonal [128,128]
__global__ void expand_rel_kernel(const float* __restrict__ rel, float* __restrict__ w) {
    int idx = blockIdx.x * blockDim.x + threadIdx.x;
    if (idx >= HC * HC) return;
    int i = idx >> 7, j = idx & 127;
    int h = i >> 5, h2 = j >> 5;
    w[idx] = (h == h2) ? rel[((h << 5) + (i & 31)) * 32 + (j & 31)] : 0.f;
}

// ---------------- matmul: C[N,128] = epi(act_in(A)[N,128] @ W[128,128] + b) -------
#define EPI_NONE 0
#define EPI_RELU 1
#define EPI_GATED 2
#define AS_STRIDE 68
#define SMEM_MM ((HC * HC + HC * AS_STRIDE) * 4)

__device__ __forceinline__ float gelu_exact(float x) {
    return 0.5f * x * (1.f + erff(x * 0.70710678118654752440f));
}

template <bool GELU_IN, bool HAS_BIAS, int EPI>
__global__ void __launch_bounds__(256, 2)
mm128_kernel(const float* __restrict__ A, const float* __restrict__ W,
             const float* __restrict__ bias, float* __restrict__ C, int N,
             const float* __restrict__ gate_p, const float* __restrict__ xprev) {
    extern __shared__ float sm[];
    float* Ws = sm;               // [128][128]
    float* As = sm + HC * HC;     // [128][AS_STRIDE] (A tile, transposed)
    int tid = threadIdx.x;
    int row0 = blockIdx.x * 64;

    // load W (64KB) fully into smem
    for (int i = tid * 4; i < HC * HC; i += 1024) {
        *(float4*)(Ws + i) = *(const float4*)(W + i);
    }
    // load A tile (64 rows x 128), transposed into As[k][r]
    for (int i = tid; i < 2048; i += 256) {
        int r = i >> 5;
        int kc = (i & 31) << 2;
        int row = row0 + r;
        float4 av = make_float4(0.f, 0.f, 0.f, 0.f);
        if (row < N) av = *(const float4*)(A + (size_t)row * HC + kc);
        if (GELU_IN) {
            av.x = gelu_exact(av.x); av.y = gelu_exact(av.y);
            av.z = gelu_exact(av.z); av.w = gelu_exact(av.w);
        }
        As[(kc + 0) * AS_STRIDE + r] = av.x;
        As[(kc + 1) * AS_STRIDE + r] = av.y;
        As[(kc + 2) * AS_STRIDE + r] = av.z;
        As[(kc + 3) * AS_STRIDE + r] = av.w;
    }
    __syncthreads();

    int tx = tid & 31;   // cols 4*tx .. 4*tx+3
    int ty = tid >> 5;   // rows 8*ty .. 8*ty+7
    const float* Ap = As + ty * 8;
    const float* Wp = Ws + tx * 4;

    float acc[8][4];
#pragma unroll
    for (int i = 0; i < 8; i++)
#pragma unroll
        for (int j = 0; j < 4; j++) acc[i][j] = 0.f;

#pragma unroll 8
    for (int k = 0; k < HC; k++) {
        float4 a0 = *(const float4*)(Ap + k * AS_STRIDE);
        float4 a1 = *(const float4*)(Ap + k * AS_STRIDE + 4);
        float4 wv = *(const float4*)(Wp + k * HC);
        float ar[8] = {a0.x, a0.y, a0.z, a0.w, a1.x, a1.y, a1.z, a1.w};
#pragma unroll
        for (int i = 0; i < 8; i++) {
            acc[i][0] += ar[i] * wv.x;
            acc[i][1] += ar[i] * wv.y;
            acc[i][2] += ar[i] * wv.z;
            acc[i][3] += ar[i] * wv.w;
        }
    }

    float4 bv = make_float4(0.f, 0.f, 0.f, 0.f);
    if (HAS_BIAS) bv = *(const float4*)(bias + tx * 4);
    float g = 0.f;
    if (EPI == EPI_GATED) g = 1.f / (1.f + expf(-*gate_p));

#pragma unroll
    for (int i = 0; i < 8; i++) {
        int row = row0 + ty * 8 + i;
        if (row >= N) continue;
        float4 r;
        r.x = acc[i][0] + bv.x;
        r.y = acc[i][1] + bv.y;
        r.z = acc[i][2] + bv.z;
        r.w = acc[i][3] + bv.w;
        if (EPI == EPI_RELU) {
            r.x = fmaxf(r.x, 0.f); r.y = fmaxf(r.y, 0.f);
            r.z = fmaxf(r.z, 0.f); r.w = fmaxf(r.w, 0.f);
        }
        if (EPI == EPI_GATED) {
            float4 xp = *(const float4*)(xprev + (size_t)row * HC + tx * 4);
            float og = 1.f - g;
            r.x = g * r.x + og * xp.x;
            r.y = g * r.y + og * xp.y;
            r.z = g * r.z + og * xp.z;
            r.w = g * r.w + og * xp.w;
        }
        *(float4*)(C + (size_t)row * HC + tx * 4) = r;
    }
}

// ---------------- attention kernels ----------------
__device__ __forceinline__ void atomicMaxFloat(float* addr, float value) {
    if (value >= 0.f)
        atomicMax((int*)addr, __float_as_int(value));
    else
        atomicMin((unsigned int*)addr, __float_as_uint(value));
}

// warp per edge: alpha[e,h] = dot(q[dst,h,:], kt[src,h,:]) * p_rel[h] / sqrt(D); amax
__global__ void attn_alpha_kernel(const float* __restrict__ q, const float* __restrict__ kt,
                                  const int* __restrict__ src, const int* __restrict__ dst,
                                  const float* __restrict__ prel,
                                  float* __restrict__ alpha, float* __restrict__ amax, int E) {
    int e = blockIdx.x * 8 + (threadIdx.x >> 5);
    if (e >= E) return;
    int lane = threadIdx.x & 31;
    int s = src[e], d = dst[e];
    float4 qv = *(const float4*)(q + (size_t)d * HC + lane * 4);
    float4 kv = *(const float4*)(kt + (size_t)s * HC + lane * 4);
    float p = qv.x * kv.x + qv.y * kv.y + qv.z * kv.z + qv.w * kv.w;
    p += __shfl_xor_sync(0xffffffffu, p, 1);
    p += __shfl_xor_sync(0xffffffffu, p, 2);
    p += __shfl_xor_sync(0xffffffffu, p, 4);
    if ((lane & 7) == 0) {
        int h = lane >> 3;
        float a = p * prel[h] * 0.17677669529663687f;  // 1/sqrt(32)
        alpha[(size_t)e * 4 + h] = a;
        atomicMaxFloat(&amax[(size_t)d * 4 + h], a);
    }
}

// thread per (edge,head): ex = exp(alpha - amax[dst]); den += ex
__global__ void attn_exp_kernel(float* __restrict__ alpha, const int* __restrict__ dst,
                                const float* __restrict__ amax, float* __restrict__ den, int E) {
    int t = blockIdx.x * blockDim.x + threadIdx.x;
    if (t >= E * 4) return;
    int e = t >> 2, h = t & 3;
    int d = dst[e];
    float ex = expf(alpha[t] - amax[(size_t)d * 4 + h]);
    alpha[t] = ex;
    atomicAdd(&den[(size_t)d * 4 + h], ex);
}

// warp per edge: agg[dst] += vt[src] * (ex / den[dst])  (float4 atomics, sm_90+)
__global__ void attn_scatter_kernel(const float* __restrict__ ex, const float* __restrict__ vt,
                                    const int* __restrict__ src, const int* __restrict__ dst,
                                    const float* __restrict__ den, float* __restrict__ agg, int E) {
    int e = blockIdx.x * 8 + (threadIdx.x >> 5);
    if (e >= E) return;
    int lane = threadIdx.x & 31;
    int s = src[e], d = dst[e];
    int h = lane >> 3;
    float w = ex[(size_t)e * 4 + h] / den[(size_t)d * 4 + h];
    float4 vv = *(const float4*)(vt + (size_t)s * HC + lane * 4);
    vv.x *= w; vv.y *= w; vv.z *= w; vv.w *= w;
    atomicAdd((float4*)(agg + (size_t)d * HC + lane * 4), vv);
}

// ---------------- output head ----------------
// warp per var node: logits = x @ W2[128,2] + b2; softmax; segment-sum into gsum/gcnt
__global__ void out_head_kernel(const float* __restrict__ X, const float* __restrict__ W2,
                                const float* __restrict__ b2, const int* __restrict__ batch,
                                float* __restrict__ gsum, float* __restrict__ gcnt, int N) {
    int n = blockIdx.x * 8 + (threadIdx.x >> 5);
    if (n >= N) return;
    int lane = threadIdx.x & 31;
    float4 x = *(const float4*)(X + (size_t)n * HC + lane * 4);
    float4 wa = *(const float4*)(W2 + lane * 8);
    float4 wb = *(const float4*)(W2 + lane * 8 + 4);
    float p0 = x.x * wa.x + x.y * wa.z + x.z * wb.x + x.w * wb.z;
    float p1 = x.x * wa.y + x.y * wa.w + x.z * wb.y + x.w * wb.w;
#pragma unroll
    for (int off = 16; off > 0; off >>= 1) {
        p0 += __shfl_xor_sync(0xffffffffu, p0, off);
        p1 += __shfl_xor_sync(0xffffffffu, p1, off);
    }
    if (lane == 0) {
        float l0 = p0 + b2[0], l1 = p1 + b2[1];
        float m = fmaxf(l0, l1);
        float e0 = expf(l0 - m), e1 = expf(l1 - m);
        float inv = 1.f / (e0 + e1);
        int g = batch[n];
        atomicAdd(&gsum[g * 2 + 0], e0 * inv);
        atomicAdd(&gsum[g * 2 + 1], e1 * inv);
        atomicAdd(&gcnt[g], 1.f);
    }
}

__global__ void finalize_kernel(const float* __restrict__ gsum, const float* __restrict__ gcnt,
                                float* __restrict__ out, int G) {
    int g = blockIdx.x * blockDim.x + threadIdx.x;
    if (g >= G) return;
    float c = fmaxf(gcnt[g], 1.f);
    out[g * 2 + 0] = gsum[g * 2 + 0] / c;
    out[g * 2 + 1] = gsum[g * 2 + 1] / c;
}

// ---------------- host orchestration ----------------
static inline void fillf(float* p, float v, int n) {
    fill_kernel<<<(n + 255) / 256, 256>>>(p, v, n);
}

#define MM(GEL, BIA, EPI, A, W, B, C, N, GATE, XP)                                     \
    mm128_kernel<GEL, BIA, EPI><<<((N) + 63) / 64, 256, SMEM_MM>>>(A, W, B, C, N, GATE, XP)

extern "C" void kernel_launch(void* const* d_in, const int* in_sizes, int n_in,
                              void* d_out, int out_size) {
    const float* x_var = (const float*)d_in[0];
    const float* x_con = (const float*)d_in[1];
    const float* mlp_in_w = (const float*)d_in[2];
    const float* mlp_in_b = (const float*)d_in[3];
    const float* w0 = (const float*)d_in[4];
    const float* b0 = (const float*)d_in[5];
    const float* w1 = (const float*)d_in[6];
    const float* b1 = (const float*)d_in[7];
    const float* w2 = (const float*)d_in[8];
    const float* b2 = (const float*)d_in[9];
    const float* k_w = (const float*)d_in[10];
    const float* k_b = (const float*)d_in[11];
    const float* q_w = (const float*)d_in[12];
    const float* q_b = (const float*)d_in[13];
    const float* v_w = (const float*)d_in[14];
    const float* v_b = (const float*)d_in[15];
    const float* a_w = (const float*)d_in[16];
    const float* a_b = (const float*)d_in[17];
    const float* skip = (const float*)d_in[18];
    const float* a_rel = (const float*)d_in[19];
    const float* m_rel = (const float*)d_in[20];
    const float* p_rel = (const float*)d_in[21];
    const int* evc = (const int*)d_in[22];
    const int* ecv = (const int*)d_in[23];
    const int* batch = (const int*)d_in[24];
    float* out = (float*)d_out;

    int Nv = in_sizes[0] / HC;
    int Nc = in_sizes[1] / HC;
    int Evc = in_sizes[22] / 2;
    int Ecv = in_sizes[23] / 2;

    float *xs0, *xs1, *tmp, *kt, *vt, *qb, *aggv, *aggc, *alpha, *amax, *den, *wea, *wem, *gsum, *gcnt;
    cudaGetSymbolAddress((void**)&xs0, g_xs0);
    cudaGetSymbolAddress((void**)&xs1, g_xs1);
    cudaGetSymbolAddress((void**)&tmp, g_tmp);
    cudaGetSymbolAddress((void**)&kt, g_kt);
    cudaGetSymbolAddress((void**)&vt, g_vt);
    cudaGetSymbolAddress((void**)&qb, g_q);
    cudaGetSymbolAddress((void**)&aggv, g_aggv);
    cudaGetSymbolAddress((void**)&aggc, g_aggc);
    cudaGetSymbolAddress((void**)&alpha, g_alpha);
    cudaGetSymbolAddress((void**)&amax, g_amax);
    cudaGetSymbolAddress((void**)&den, g_den);
    cudaGetSymbolAddress((void**)&wea, g_wea);
    cudaGetSymbolAddress((void**)&wem, g_wem);
    cudaGetSymbolAddress((void**)&gsum, g_gsum);
    cudaGetSymbolAddress((void**)&gcnt, g_gcnt);

    // opt-in >48KB dynamic smem for every instantiation used (idempotent)
    cudaFuncSetAttribute(mm128_kernel<false, true, EPI_RELU>,
                         cudaFuncAttributeMaxDynamicSharedMemorySize, SMEM_MM);
    cudaFuncSetAttribute(mm128_kernel<false, true, EPI_NONE>,
                         cudaFuncAttributeMaxDynamicSharedMemorySize, SMEM_MM);
    cudaFuncSetAttribute(mm128_kernel<false, false, EPI_NONE>,
                         cudaFuncAttributeMaxDynamicSharedMemorySize, SMEM_MM);
    cudaFuncSetAttribute(mm128_kernel<true, true, EPI_GATED>,
                         cudaFuncAttributeMaxDynamicSharedMemorySize, SMEM_MM);

    // ---- input MLPs (3 layers each, relu on first two) ----
    MM(false, true, EPI_RELU, x_var, mlp_in_w + 0 * 16384, mlp_in_b + 0 * 128, xs0, Nv, nullptr, nullptr);
    MM(false, true, EPI_RELU, xs0,   mlp_in_w + 1 * 16384, mlp_in_b + 1 * 128, xs0, Nv, nullptr, nullptr);
    MM(false, true, EPI_NONE, xs0,   mlp_in_w + 2 * 16384, mlp_in_b + 2 * 128, xs0, Nv, nullptr, nullptr);
    MM(false, true, EPI_RELU, x_con, mlp_in_w + 3 * 16384, mlp_in_b + 3 * 128, xs1, Nc, nullptr, nullptr);
    MM(false, true, EPI_RELU, xs1,   mlp_in_w + 4 * 16384, mlp_in_b + 4 * 128, xs1, Nc, nullptr, nullptr);
    MM(false, true, EPI_NONE, xs1,   mlp_in_w + 5 * 16384, mlp_in_b + 5 * 128, xs1, Nc, nullptr, nullptr);

    // ---- HGTConv layers ----
    for (int l = 0; l < LAYERS; l++) {
        // per-edge-type attention. et=0: var->con (src type 0, dst type 1, dst count Nc)
        //                           et=1: con->var (src type 1, dst type 0, dst count Nv)
        for (int et = 0; et < 2; et++) {
            int st = (et == 0) ? 0 : 1;        // src node type
            int dt = (et == 0) ? 1 : 0;        // dst node type
            const float* xs_s = (st == 0) ? xs0 : xs1;
            const float* xs_d = (dt == 0) ? xs0 : xs1;
            int Ns = (st == 0) ? Nv : Nc;
            int Nd = (dt == 0) ? Nv : Nc;
            const int* edges = (et == 0) ? evc : ecv;
            int E = (et == 0) ? Evc : Ecv;
            const int* esrc = edges;
            const int* edst = edges + E;
            float* agg = (dt == 0) ? aggv : aggc;
            int wi = l * 2;

            // K = xs_s @ k_w[l,st] + k_b ; kt = K @ blockdiag(a_rel[l,et])
            MM(false, true, EPI_NONE, xs_s, k_w + (size_t)(wi + st) * 16384,
               k_b + (wi + st) * 128, tmp, Ns, nullptr, nullptr);
            expand_rel_kernel<<<64, 256>>>(a_rel + (size_t)(wi + et) * 4096, wea);
            MM(false, false, EPI_NONE, tmp, wea, nullptr, kt, Ns, nullptr, nullptr);

            // V = xs_s @ v_w[l,st] + v_b ; vt = V @ blockdiag(m_rel[l,et])
            MM(false, true, EPI_NONE, xs_s, v_w + (size_t)(wi + st) * 16384,
               v_b + (wi + st) * 128, tmp, Ns, nullptr, nullptr);
            expand_rel_kernel<<<64, 256>>>(m_rel + (size_t)(wi + et) * 4096, wem);
            MM(false, false, EPI_NONE, tmp, wem, nullptr, vt, Ns, nullptr, nullptr);

            // Q = xs_d @ q_w[l,dt] + q_b
            MM(false, true, EPI_NONE, xs_d, q_w + (size_t)(wi + dt) * 16384,
               q_b + (wi + dt) * 128, qb, Nd, nullptr, nullptr);

            // segment softmax + scatter
            fillf(amax, -INFINITY, Nd * 4);
            fillf(den, 0.f, Nd * 4);
            fillf(agg, 0.f, Nd * HC);
            attn_alpha_kernel<<<(E + 7) / 8, 256>>>(qb, kt, esrc, edst,
                                                    p_rel + (size_t)(wi + et) * 4,
                                                    alpha, amax, E);
            attn_exp_kernel<<<(E * 4 + 255) / 256, 256>>>(alpha, edst, amax, den, E);
            attn_scatter_kernel<<<(E + 7) / 8, 256>>>(alpha, vt, esrc, edst, den, agg, E);
        }

        // gated update per node type: xs = g*(gelu(agg) @ a_w + a_b) + (1-g)*xs
        int wi = l * 2;
        MM(true, true, EPI_GATED, aggv, a_w + (size_t)(wi + 0) * 16384,
           a_b + (wi + 0) * 128, xs0, Nv, skip + wi + 0, xs0);
        MM(true, true, EPI_GATED, aggc, a_w + (size_t)(wi + 1) * 16384,
           a_b + (wi + 1) * 128, xs1, Nc, skip + wi + 1, xs1);
    }

    // ---- output head: MLP -> softmax -> segment mean ----
    MM(false, true, EPI_RELU, xs0, w0, b0, tmp, Nv, nullptr, nullptr);
    MM(false, true, EPI_RELU, tmp, w1, b1, tmp, Nv, nullptr, nullptr);
    fillf(gsum, 0.f, NG * 2);
    fillf(gcnt, 0.f, NG);
    out_head_kernel<<<(Nv + 7) / 8, 256>>>(tmp, w2, b2, batch, gsum, gcnt, Nv);
    finalize_kernel<<<(NG + 255) / 256, 256>>>(gsum, gcnt, out, NG);
}

// round 3
// speedup vs baseline: 1.1233x; 1.1233x over previous
#include <cuda_runtime.h>
#include <cuda_bf16.h>
#include <math.h>
#include <stdint.h>

#define HC 128
#define NVMAX 50000
#define NEMAX 400000
#define NG 512
#define LAYERS 2
#define NW 24

// packed weight image: [n][k] bf16, row stride 136 (pad 8), hi then lo
#define WROW 136
#define WIMG_ELEMS (128 * WROW)            // 17408 bf16 per (hi|lo) image
#define WIMG_BYTES (WIMG_ELEMS * 2)        // 34816 B

// ---------------- scratch (device globals; no allocation) ----------------
__device__ float g_xs0[NVMAX * HC];
__device__ float g_xs1[NVMAX * HC];
__device__ float g_tmp[NVMAX * HC];
__device__ float g_kt[NVMAX * HC];
__device__ float g_vt[NVMAX * HC];
__device__ float g_q[NVMAX * HC];
__device__ float g_aggv[NVMAX * HC];
__device__ float g_aggc[NVMAX * HC];
__device__ float g_alpha[NEMAX * 4];
__device__ float g_amax[NVMAX * 4];
__device__ float g_den[NVMAX * 4];
__device__ __align__(16) __nv_bfloat16 g_wimg[NW * 2 * WIMG_ELEMS];
__device__ float g_bcomp[8 * HC];
__device__ float g_gsum[NG * 2];
__device__ float g_gcnt[NG];

// ---------------- helpers ----------------
__device__ __forceinline__ uint32_t smem_u32(const void* p) {
    uint32_t a;
    asm("{ .reg .u64 t; cvta.to.shared.u64 t, %1; cvt.u32.u64 %0, t; }" : "=r"(a) : "l"(p));
    return a;
}
__device__ __forceinline__ void bsplit(float x, __nv_bfloat16& h, __nv_bfloat16& l) {
    h = __float2bfloat16(x);
    l = __float2bfloat16(x - __bfloat162float(h));
}
__device__ __forceinline__ float gelu_exact(float x) {
    return 0.5f * x * (1.f + erff(x * 0.70710678118654752440f));
}
__device__ __forceinline__ void ldm_x4(uint32_t* r, uint32_t addr) {
    asm volatile("ldmatrix.sync.aligned.m8n8.x4.shared.b16 {%0,%1,%2,%3}, [%4];"
                 : "=r"(r[0]), "=r"(r[1]), "=r"(r[2]), "=r"(r[3]) : "r"(addr));
}
__device__ __forceinline__ void ldm_x2(uint32_t* r, uint32_t addr) {
    asm volatile("ldmatrix.sync.aligned.m8n8.x2.shared.b16 {%0,%1}, [%2];"
                 : "=r"(r[0]), "=r"(r[1]) : "r"(addr));
}
__device__ __forceinline__ void mma16816(float* c, const uint32_t* a, const uint32_t* b) {
    asm volatile("mma.sync.aligned.m16n8k16.row.col.f32.bf16.bf16.f32 "
                 "{%0,%1,%2,%3}, {%4,%5,%6,%7}, {%8,%9}, {%0,%1,%2,%3};"
                 : "+f"(c[0]), "+f"(c[1]), "+f"(c[2]), "+f"(c[3])
                 : "r"(a[0]), "r"(a[1]), "r"(a[2]), "r"(a[3]), "r"(b[0]), "r"(b[1]));
}

// ---------------- weight pre-pack (compose + split, [n][k] stride-136) ------
struct PackJobs {
    const float* w[NW];    // [128,128] row-major (k, n)
    const float* rel[NW];  // [4,32,32] or null
    const float* bin[NW];
    float* bout[NW];
};

__global__ void pack_kernel(PackJobs jobs, __nv_bfloat16* img) {
    int j = blockIdx.x;
    int tid = threadIdx.x;
    const float* w = jobs.w[j];
    const float* rel = jobs.rel[j];
    __shared__ float rs[4096];
    if (rel) {
        for (int i = tid; i < 4096; i += 256) rs[i] = rel[i];
        __syncthreads();
    }
    __nv_bfloat16* ih = img + (size_t)j * 2 * WIMG_ELEMS;
    __nv_bfloat16* il = ih + WIMG_ELEMS;
    for (int idx = tid; idx < 16384; idx += 256) {
        int k = idx >> 7, n = idx & 127;
        float val;
        if (rel) {
            int h = n >> 5, nn = n & 31;
            const float* wr = w + k * 128 + h * 32;
            const float* rr = rs + h * 1024 + nn;
            float s = 0.f;
#pragma unroll
            for (int jj = 0; jj < 32; jj++) s += wr[jj] * rr[jj * 32];
            val = s;
        } else {
            val = w[k * 128 + n];
        }
        __nv_bfloat16 h, l;
        bsplit(val, h, l);
        ih[n * WROW + k] = h;
        il[n * WROW + k] = l;
    }
    if (rel && jobs.bout[j] && tid < 128) {
        int h = tid >> 5, nn = tid & 31;
        const float* b = jobs.bin[j];
        float s = 0.f;
#pragma unroll
        for (int jj = 0; jj < 32; jj++) s += b[h * 32 + jj] * rs[h * 1024 + jj * 32 + nn];
        jobs.bout[j][tid] = s;
    }
}

// ---------------- mma.sync GEMM: C[N,128] = epi(act(A) @ W + b) --------------
#define EPI_NONE 0
#define EPI_RELU 1
#define EPI_GATED 2

#define SM_AHI 0
#define SM_ALO WIMG_BYTES
#define SM_WHI (2 * WIMG_BYTES)
#define SM_WLO (3 * WIMG_BYTES)
#define SMEM_MM (4 * WIMG_BYTES)   // 139264 B

template <bool GELU_IN, int EPI>
__global__ void __launch_bounds__(256, 1)
mm_mma_kernel(const float* __restrict__ A, const __nv_bfloat16* __restrict__ Wimg,
              const float* __restrict__ bias, float* __restrict__ C, int N,
              const float* __restrict__ gate_p, const float* __restrict__ xprev) {
    extern __shared__ char smem[];
    int tid = threadIdx.x;
    int wid = tid >> 5;
    int lane = tid & 31;
    int row0 = blockIdx.x * 128;

    // copy pre-packed W hi+lo (69632 B)
    {
        const float4* wg = (const float4*)Wimg;
        float4* ws = (float4*)(smem + SM_WHI);
        for (int i = tid; i < 4352; i += 256) ws[i] = wg[i];
    }
    // convert A tile -> bf16 hi/lo, [r][k] stride 136
    for (int it = 0; it < 16; ++it) {
        int i = tid + it * 256;
        int r = i >> 5;
        int k = (i & 31) * 4;
        float4 av = make_float4(0.f, 0.f, 0.f, 0.f);
        int row = row0 + r;
        if (row < N) av = *(const float4*)(A + (size_t)row * HC + k);
        if (GELU_IN) {
            av.x = gelu_exact(av.x); av.y = gelu_exact(av.y);
            av.z = gelu_exact(av.z); av.w = gelu_exact(av.w);
        }
        __nv_bfloat16 h0, h1, h2, h3, l0, l1, l2, l3;
        bsplit(av.x, h0, l0); bsplit(av.y, h1, l1);
        bsplit(av.z, h2, l2); bsplit(av.w, h3, l3);
        uint32_t off = (uint32_t)(r * WROW + k) * 2;
        __nv_bfloat162 p;
        p.x = h0; p.y = h1; *(__nv_bfloat162*)(smem + SM_AHI + off) = p;
        p.x = h2; p.y = h3; *(__nv_bfloat162*)(smem + SM_AHI + off + 4) = p;
        p.x = l0; p.y = l1; *(__nv_bfloat162*)(smem + SM_ALO + off) = p;
        p.x = l2; p.y = l3; *(__nv_bfloat162*)(smem + SM_ALO + off + 4) = p;
    }
    __syncthreads();

    int warpM = wid >> 1;           // 0..3 -> 32 rows each
    int warpN = wid & 1;            // 0..1 -> 64 cols each
    uint32_t sb = smem_u32(smem);
    // ldmatrix lane addresses (A: x4 over rows (lane&15), k-half (lane>>4))
    uint32_t a_lane = sb + SM_AHI +
        ((uint32_t)((warpM * 32 + (lane & 15)) * WROW + ((lane >> 4) << 3)) << 1);
    uint32_t b_lane = sb + SM_WHI +
        ((uint32_t)((warpN * 64 + (lane & 7)) * WROW + (((lane >> 3) & 1) << 3)) << 1);

    float acc[2][8][4];
#pragma unroll
    for (int i = 0; i < 2; i++)
#pragma unroll
        for (int j = 0; j < 8; j++)
#pragma unroll
            for (int q = 0; q < 4; q++) acc[i][j][q] = 0.f;

#pragma unroll
    for (int p = 0; p < 3; p++) {
        uint32_t abase = a_lane + (p == 2 ? (uint32_t)WIMG_BYTES : 0u);
        uint32_t bbase = b_lane + (p == 1 ? (uint32_t)WIMG_BYTES : 0u);
#pragma unroll
        for (int ks = 0; ks < 8; ks++) {
            uint32_t ar[2][4];
            ldm_x4(ar[0], abase + ks * 32);
            ldm_x4(ar[1], abase + ks * 32 + 16 * WROW * 2);
#pragma unroll
            for (int nt = 0; nt < 8; nt++) {
                uint32_t br[2];
                ldm_x2(br, bbase + ks * 32 + nt * 8 * WROW * 2);
                mma16816(acc[0][nt], ar[0], br);
                mma16816(acc[1][nt], ar[1], br);
            }
        }
    }

    // epilogue
    int gid = lane >> 2, tq = lane & 3;
    float g = 0.f, og = 0.f;
    if (EPI == EPI_GATED) { g = 1.f / (1.f + expf(-*gate_p)); og = 1.f - g; }
#pragma unroll
    for (int mt = 0; mt < 2; mt++) {
#pragma unroll
        for (int nt = 0; nt < 8; nt++) {
            int col = warpN * 64 + nt * 8 + tq * 2;
            float2 bv = *(const float2*)(bias + col);
#pragma unroll
            for (int half = 0; half < 2; half++) {
                int row = row0 + warpM * 32 + mt * 16 + gid + half * 8;
                if (row >= N) continue;
                float c0 = acc[mt][nt][half * 2 + 0] + bv.x;
                float c1 = acc[mt][nt][half * 2 + 1] + bv.y;
                if (EPI == EPI_RELU) { c0 = fmaxf(c0, 0.f); c1 = fmaxf(c1, 0.f); }
                if (EPI == EPI_GATED) {
                    float2 xp = *(const float2*)(xprev + (size_t)row * HC + col);
                    c0 = g * c0 + og * xp.x;
                    c1 = g * c1 + og * xp.y;
                }
                *(float2*)(C + (size_t)row * HC + col) = make_float2(c0, c1);
            }
        }
    }
}

// ---------------- small utility kernels ----------------
__global__ void fill_kernel(float* __restrict__ p, float v, int n) {
    int i = blockIdx.x * blockDim.x + threadIdx.x;
    if (i < n) p[i] = v;
}

// ---------------- attention kernels (validated round 1) ----------------
__device__ __forceinline__ void atomicMaxFloat(float* addr, float value) {
    if (value >= 0.f)
        atomicMax((int*)addr, __float_as_int(value));
    else
        atomicMin((unsigned int*)addr, __float_as_uint(value));
}

__global__ void attn_alpha_kernel(const float* __restrict__ q, const float* __restrict__ kt,
                                  const int* __restrict__ src, const int* __restrict__ dst,
                                  const float* __restrict__ prel,
                                  float* __restrict__ alpha, float* __restrict__ amax, int E) {
    int e = blockIdx.x * 8 + (threadIdx.x >> 5);
    if (e >= E) return;
    int lane = threadIdx.x & 31;
    int s = src[e], d = dst[e];
    float4 qv = *(const float4*)(q + (size_t)d * HC + lane * 4);
    float4 kv = *(const float4*)(kt + (size_t)s * HC + lane * 4);
    float p = qv.x * kv.x + qv.y * kv.y + qv.z * kv.z + qv.w * kv.w;
    p += __shfl_xor_sync(0xffffffffu, p, 1);
    p += __shfl_xor_sync(0xffffffffu, p, 2);
    p += __shfl_xor_sync(0xffffffffu, p, 4);
    if ((lane & 7) == 0) {
        int h = lane >> 3;
        float a = p * prel[h] * 0.17677669529663687f;
        alpha[(size_t)e * 4 + h] = a;
        atomicMaxFloat(&amax[(size_t)d * 4 + h], a);
    }
}

__global__ void attn_exp_kernel(float* __restrict__ alpha, const int* __restrict__ dst,
                                const float* __restrict__ amax, float* __restrict__ den, int E) {
    int t = blockIdx.x * blockDim.x + threadIdx.x;
    if (t >= E * 4) return;
    int e = t >> 2, h = t & 3;
    int d = dst[e];
    float ex = expf(alpha[t] - amax[(size_t)d * 4 + h]);
    alpha[t] = ex;
    atomicAdd(&den[(size_t)d * 4 + h], ex);
}

__global__ void attn_scatter_kernel(const float* __restrict__ ex, const float* __restrict__ vt,
                                    const int* __restrict__ src, const int* __restrict__ dst,
                                    const float* __restrict__ den, float* __restrict__ agg, int E) {
    int e = blockIdx.x * 8 + (threadIdx.x >> 5);
    if (e >= E) return;
    int lane = threadIdx.x & 31;
    int s = src[e], d = dst[e];
    int h = lane >> 3;
    float w = ex[(size_t)e * 4 + h] / den[(size_t)d * 4 + h];
    float4 vv = *(const float4*)(vt + (size_t)s * HC + lane * 4);
    vv.x *= w; vv.y *= w; vv.z *= w; vv.w *= w;
    atomicAdd((float4*)(agg + (size_t)d * HC + lane * 4), vv);
}

// ---------------- output head ----------------
__global__ void out_head_kernel(const float* __restrict__ X, const float* __restrict__ W2,
                                const float* __restrict__ b2, const int* __restrict__ batch,
                                float* __restrict__ gsum, float* __restrict__ gcnt, int N) {
    int n = blockIdx.x * 8 + (threadIdx.x >> 5);
    if (n >= N) return;
    int lane = threadIdx.x & 31;
    float4 x = *(const float4*)(X + (size_t)n * HC + lane * 4);
    float4 wa = *(const float4*)(W2 + lane * 8);
    float4 wb = *(const float4*)(W2 + lane * 8 + 4);
    float p0 = x.x * wa.x + x.y * wa.z + x.z * wb.x + x.w * wb.z;
    float p1 = x.x * wa.y + x.y * wa.w + x.z * wb.y + x.w * wb.w;
#pragma unroll
    for (int off = 16; off > 0; off >>= 1) {
        p0 += __shfl_xor_sync(0xffffffffu, p0, off);
        p1 += __shfl_xor_sync(0xffffffffu, p1, off);
    }
    if (lane == 0) {
        float l0 = p0 + b2[0], l1 = p1 + b2[1];
        float m = fmaxf(l0, l1);
        float e0 = expf(l0 - m), e1 = expf(l1 - m);
        float inv = 1.f / (e0 + e1);
        int g = batch[n];
        atomicAdd(&gsum[g * 2 + 0], e0 * inv);
        atomicAdd(&gsum[g * 2 + 1], e1 * inv);
        atomicAdd(&gcnt[g], 1.f);
    }
}

__global__ void finalize_kernel(const float* __restrict__ gsum, const float* __restrict__ gcnt,
                                float* __restrict__ out, int G) {
    int g = blockIdx.x * blockDim.x + threadIdx.x;
    if (g >= G) return;
    float c = fmaxf(gcnt[g], 1.f);
    out[g * 2 + 0] = gsum[g * 2 + 0] / c;
    out[g * 2 + 1] = gsum[g * 2 + 1] / c;
}

// ---------------- host orchestration ----------------
static inline void fillf(float* p, float v, int n) {
    fill_kernel<<<(n + 255) / 256, 256>>>(p, v, n);
}

#define IMG(j) (wimg + (size_t)(j) * 2 * WIMG_ELEMS)
#define MMTC(GEL, EPI, A, J, B, C, N, GATE, XP)                                    \
    mm_mma_kernel<GEL, EPI><<<((N) + 127) / 128, 256, SMEM_MM>>>(A, IMG(J), B, C, N, GATE, XP)

extern "C" void kernel_launch(void* const* d_in, const int* in_sizes, int n_in,
                              void* d_out, int out_size) {
    const float* x_var = (const float*)d_in[0];
    const float* x_con = (const float*)d_in[1];
    const float* mlp_in_w = (const float*)d_in[2];
    const float* mlp_in_b = (const float*)d_in[3];
    const float* w0 = (const float*)d_in[4];
    const float* b0 = (const float*)d_in[5];
    const float* w1 = (const float*)d_in[6];
    const float* b1 = (const float*)d_in[7];
    const float* w2 = (const float*)d_in[8];
    const float* b2 = (const float*)d_in[9];
    const float* k_w = (const float*)d_in[10];
    const float* k_b = (const float*)d_in[11];
    const float* q_w = (const float*)d_in[12];
    const float* q_b = (const float*)d_in[13];
    const float* v_w = (const float*)d_in[14];
    const float* v_b = (const float*)d_in[15];
    const float* a_w = (const float*)d_in[16];
    const float* a_b = (const float*)d_in[17];
    const float* skip = (const float*)d_in[18];
    const float* a_rel = (const float*)d_in[19];
    const float* m_rel = (const float*)d_in[20];
    const float* p_rel = (const float*)d_in[21];
    const int* evc = (const int*)d_in[22];
    const int* ecv = (const int*)d_in[23];
    const int* batch = (const int*)d_in[24];
    float* out = (float*)d_out;

    int Nv = in_sizes[0] / HC;
    int Nc = in_sizes[1] / HC;
    int Evc = in_sizes[22] / 2;
    int Ecv = in_sizes[23] / 2;

    float *xs0, *xs1, *tmp, *kt, *vt, *qb, *aggv, *aggc, *alpha, *amax, *den, *bcomp, *gsum, *gcnt;
    __nv_bfloat16* wimg;
    cudaGetSymbolAddress((void**)&xs0, g_xs0);
    cudaGetSymbolAddress((void**)&xs1, g_xs1);
    cudaGetSymbolAddress((void**)&tmp, g_tmp);
    cudaGetSymbolAddress((void**)&kt, g_kt);
    cudaGetSymbolAddress((void**)&vt, g_vt);
    cudaGetSymbolAddress((void**)&qb, g_q);
    cudaGetSymbolAddress((void**)&aggv, g_aggv);
    cudaGetSymbolAddress((void**)&aggc, g_aggc);
    cudaGetSymbolAddress((void**)&alpha, g_alpha);
    cudaGetSymbolAddress((void**)&amax, g_amax);
    cudaGetSymbolAddress((void**)&den, g_den);
    cudaGetSymbolAddress((void**)&wimg, g_wimg);
    cudaGetSymbolAddress((void**)&bcomp, g_bcomp);
    cudaGetSymbolAddress((void**)&gsum, g_gsum);
    cudaGetSymbolAddress((void**)&gcnt, g_gcnt);

    cudaFuncSetAttribute(mm_mma_kernel<false, EPI_NONE>,
                         cudaFuncAttributeMaxDynamicSharedMemorySize, SMEM_MM);
    cudaFuncSetAttribute(mm_mma_kernel<false, EPI_RELU>,
                         cudaFuncAttributeMaxDynamicSharedMemorySize, SMEM_MM);
    cudaFuncSetAttribute(mm_mma_kernel<true, EPI_GATED>,
                         cudaFuncAttributeMaxDynamicSharedMemorySize, SMEM_MM);

    // ---- weight packing jobs ----
    PackJobs pj;
    for (int j = 0; j < NW; j++) { pj.w[j] = nullptr; pj.rel[j] = nullptr; pj.bin[j] = nullptr; pj.bout[j] = nullptr; }
    for (int t = 0; t < 2; t++)
        for (int i = 0; i < 3; i++) pj.w[t * 3 + i] = mlp_in_w + (size_t)(t * 3 + i) * 16384;
    for (int l = 0; l < LAYERS; l++)
        for (int et = 0; et < 2; et++) {
            int li = l * 2 + et;
            pj.w[6 + li] = k_w + (size_t)li * 16384;
            pj.rel[6 + li] = a_rel + (size_t)li * 4096;
            pj.bin[6 + li] = k_b + (size_t)li * 128;
            pj.bout[6 + li] = bcomp + (size_t)li * 128;
            pj.w[10 + li] = v_w + (size_t)li * 16384;
            pj.rel[10 + li] = m_rel + (size_t)li * 4096;
            pj.bin[10 + li] = v_b + (size_t)li * 128;
            pj.bout[10 + li] = bcomp + (size_t)(4 + li) * 128;
            pj.w[14 + li] = q_w + (size_t)li * 16384;
            pj.w[18 + li] = a_w + (size_t)li * 16384;
        }
    pj.w[22] = w0;
    pj.w[23] = w1;
    pack_kernel<<<NW, 256>>>(pj, wimg);

    // ---- input MLPs ----
    MMTC(false, EPI_RELU, x_var, 0, mlp_in_b + 0 * 128, xs0, Nv, nullptr, nullptr);
    MMTC(false, EPI_RELU, xs0,   1, mlp_in_b + 1 * 128, xs0, Nv, nullptr, nullptr);
    MMTC(false, EPI_NONE, xs0,   2, mlp_in_b + 2 * 128, xs0, Nv, nullptr, nullptr);
    MMTC(false, EPI_RELU, x_con, 3, mlp_in_b + 3 * 128, xs1, Nc, nullptr, nullptr);
    MMTC(false, EPI_RELU, xs1,   4, mlp_in_b + 4 * 128, xs1, Nc, nullptr, nullptr);
    MMTC(false, EPI_NONE, xs1,   5, mlp_in_b + 5 * 128, xs1, Nc, nullptr, nullptr);

    // ---- HGTConv layers ----
    for (int l = 0; l < LAYERS; l++) {
        for (int et = 0; et < 2; et++) {
            int st = et, dt = 1 - et;
            const float* xs_s = (st == 0) ? xs0 : xs1;
            const float* xs_d = (dt == 0) ? xs0 : xs1;
            int Ns = (st == 0) ? Nv : Nc;
            int Nd = (dt == 0) ? Nv : Nc;
            const int* edges = (et == 0) ? evc : ecv;
            int E = (et == 0) ? Evc : Ecv;
            const int* esrc = edges;
            const int* edst = edges + E;
            float* agg = (dt == 0) ? aggv : aggc;
            int li = l * 2 + et;

            MMTC(false, EPI_NONE, xs_s, 6 + li, bcomp + (size_t)li * 128, kt, Ns, nullptr, nullptr);
            MMTC(false, EPI_NONE, xs_s, 10 + li, bcomp + (size_t)(4 + li) * 128, vt, Ns, nullptr, nullptr);
            MMTC(false, EPI_NONE, xs_d, 14 + l * 2 + dt, q_b + (size_t)(l * 2 + dt) * 128, qb, Nd, nullptr, nullptr);

            fillf(amax, -INFINITY, Nd * 4);
            fillf(den, 0.f, Nd * 4);
            fillf(agg, 0.f, Nd * HC);
            attn_alpha_kernel<<<(E + 7) / 8, 256>>>(qb, kt, esrc, edst,
                                                    p_rel + (size_t)li * 4, alpha, amax, E);
            attn_exp_kernel<<<(E * 4 + 255) / 256, 256>>>(alpha, edst, amax, den, E);
            attn_scatter_kernel<<<(E + 7) / 8, 256>>>(alpha, vt, esrc, edst, den, agg, E);
        }
        MMTC(true, EPI_GATED, aggv, 18 + l * 2 + 0, a_b + (size_t)(l * 2 + 0) * 128,
             xs0, Nv, skip + l * 2 + 0, xs0);
        MMTC(true, EPI_GATED, aggc, 18 + l * 2 + 1, a_b + (size_t)(l * 2 + 1) * 128,
             xs1, Nc, skip + l * 2 + 1, xs1);
    }

    // ---- output head ----
    MMTC(false, EPI_RELU, xs0, 22, b0, tmp, Nv, nullptr, nullptr);
    MMTC(false, EPI_RELU, tmp, 23, b1, tmp, Nv, nullptr, nullptr);
    fillf(gsum, 0.f, NG * 2);
    fillf(gcnt, 0.f, NG);
    out_head_kernel<<<(Nv + 7) / 8, 256>>>(tmp, w2, b2, batch, gsum, gcnt, Nv);
    finalize_kernel<<<(NG + 255) / 256, 256>>>(gsum, gcnt, out, NG);
}

// round 4
// speedup vs baseline: 2.0199x; 1.7983x over previous
#include <cuda_runtime.h>
#include <cuda_bf16.h>
#include <math.h>
#include <stdint.h>

#define HC 128
#define NVMAX 50000
#define NEMAX 400000
#define NG 512
#define LAYERS 2
#define NW 24

// packed weight image: [n][k] bf16, row stride 136 (pad 8), hi then lo
#define WROW 136
#define WIMG_ELEMS (128 * WROW)            // 17408 bf16 per (hi|lo) image
#define WIMG_BYTES (WIMG_ELEMS * 2)        // 34816 B

// ---------------- scratch (device globals; no allocation) ----------------
__device__ float g_xs0[NVMAX * HC];
__device__ float g_xs1[NVMAX * HC];
__device__ float g_tmp[NVMAX * HC];
__device__ float g_kt[NVMAX * HC];
__device__ float g_vt[NVMAX * HC];
__device__ float g_q[NVMAX * HC];
__device__ float g_aggv[NVMAX * HC];
__device__ float g_aggc[NVMAX * HC];
__device__ float g_alpha[NEMAX * 4];
__device__ float g_amax[NVMAX * 4];
__device__ float g_den0[NVMAX * 4];   // dst = var
__device__ float g_den1[NVMAX * 4];   // dst = con
__device__ __align__(16) __nv_bfloat16 g_wimg[NW * 2 * WIMG_ELEMS];
__device__ float g_bcomp[8 * HC];
__device__ float g_gsum[NG * 2];
__device__ float g_gcnt[NG];

// ---------------- helpers ----------------
__device__ __forceinline__ uint32_t smem_u32(const void* p) {
    uint32_t a;
    asm("{ .reg .u64 t; cvta.to.shared.u64 t, %1; cvt.u32.u64 %0, t; }" : "=r"(a) : "l"(p));
    return a;
}
__device__ __forceinline__ void bsplit(float x, __nv_bfloat16& h, __nv_bfloat16& l) {
    h = __float2bfloat16(x);
    l = __float2bfloat16(x - __bfloat162float(h));
}
__device__ __forceinline__ float gelu_exact(float x) {
    return 0.5f * x * (1.f + erff(x * 0.70710678118654752440f));
}
__device__ __forceinline__ void ldm_x4(uint32_t* r, uint32_t addr) {
    asm volatile("ldmatrix.sync.aligned.m8n8.x4.shared.b16 {%0,%1,%2,%3}, [%4];"
                 : "=r"(r[0]), "=r"(r[1]), "=r"(r[2]), "=r"(r[3]) : "r"(addr));
}
__device__ __forceinline__ void mma16816(float* c, const uint32_t* a, const uint32_t* b) {
    asm volatile("mma.sync.aligned.m16n8k16.row.col.f32.bf16.bf16.f32 "
                 "{%0,%1,%2,%3}, {%4,%5,%6,%7}, {%8,%9}, {%0,%1,%2,%3};"
                 : "+f"(c[0]), "+f"(c[1]), "+f"(c[2]), "+f"(c[3])
                 : "r"(a[0]), "r"(a[1]), "r"(a[2]), "r"(a[3]), "r"(b[0]), "r"(b[1]));
}
__device__ __forceinline__ void cp_async16(uint32_t saddr, const void* gaddr) {
    asm volatile("cp.async.cg.shared.global [%0], [%1], 16;" :: "r"(saddr), "l"(gaddr));
}

// ---------------- weight pre-pack (compose + split, [n][k] stride-136) ------
struct PackJobs {
    const float* w[NW];    // [128,128] row-major (k, n)
    const float* rel[NW];  // [4,32,32] or null
    const float* bin[NW];
    float* bout[NW];
};

__global__ void pack_kernel(PackJobs jobs, __nv_bfloat16* img) {
    int j = blockIdx.x;
    int part = blockIdx.y;
    int tid = threadIdx.x;
    const float* w = jobs.w[j];
    const float* rel = jobs.rel[j];
    __shared__ float rs[4096];
    if (rel) {
        for (int i = tid; i < 4096; i += 256) rs[i] = rel[i];
        __syncthreads();
    }
    __nv_bfloat16* ih = img + (size_t)j * 2 * WIMG_ELEMS;
    __nv_bfloat16* il = ih + WIMG_ELEMS;
    for (int idx = part * 4096 + tid; idx < (part + 1) * 4096; idx += 256) {
        int k = idx >> 7, n = idx & 127;
        float val;
        if (rel) {
            int h = n >> 5, nn = n & 31;
            const float* wr = w + k * 128 + h * 32;
            const float* rr = rs + h * 1024 + nn;
            float s = 0.f;
#pragma unroll
            for (int jj = 0; jj < 32; jj++) s += wr[jj] * rr[jj * 32];
            val = s;
        } else {
            val = w[k * 128 + n];
        }
        __nv_bfloat16 h, l;
        bsplit(val, h, l);
        ih[n * WROW + k] = h;
        il[n * WROW + k] = l;
    }
    if (part == 0 && rel && jobs.bout[j] && tid < 128) {
        int h = tid >> 5, nn = tid & 31;
        const float* b = jobs.bin[j];
        float s = 0.f;
#pragma unroll
        for (int jj = 0; jj < 32; jj++) s += b[h * 32 + jj] * rs[h * 1024 + jj * 32 + nn];
        jobs.bout[j][tid] = s;
    }
}

// ---------------- mma.sync GEMM: C[N,128] = epi(act(A) @ W + b) --------------
// NORM: A is divided per-row/per-head by den then gelu'd (fused softmax norm)
#define EPI_NONE 0
#define EPI_RELU 1
#define EPI_GATED 2

#define SM_AHI 0
#define SM_ALO WIMG_BYTES
#define SM_WHI (2 * WIMG_BYTES)
#define SM_WLO (3 * WIMG_BYTES)
#define SMEM_MM (4 * WIMG_BYTES)   // 139264 B

template <bool NORM, int EPI>
__global__ void __launch_bounds__(512, 1)
mm_mma_kernel(const float* __restrict__ A, const __nv_bfloat16* __restrict__ Wimg,
              const float* __restrict__ bias, float* __restrict__ C, int N,
              const float* __restrict__ gate_p, const float* __restrict__ xprev,
              const float* __restrict__ den) {
    extern __shared__ char smem[];
    int tid = threadIdx.x;
    int wid = tid >> 5;
    int lane = tid & 31;
    int row0 = blockIdx.x * 128;
    uint32_t sb = smem_u32(smem);

    // async-copy pre-packed W hi+lo (69632 B) while we convert A
    for (int i = tid; i < 4352; i += 512)
        cp_async16(sb + SM_WHI + i * 16, (const float4*)Wimg + i);
    asm volatile("cp.async.commit_group;" ::: "memory");

    // convert A tile -> bf16 hi/lo, [r][k] stride 136 (register path)
    for (int it = 0; it < 8; ++it) {
        int i = tid + it * 512;
        int r = i >> 5;
        int k = (i & 31) * 4;
        float4 av = make_float4(0.f, 0.f, 0.f, 0.f);
        int row = row0 + r;
        if (row < N) av = *(const float4*)(A + (size_t)row * HC + k);
        if (NORM) {
            float rcp = 1.f / fmaxf(den[(size_t)row * 4 + (k >> 5)], 1e-37f);
            av.x = gelu_exact(av.x * rcp); av.y = gelu_exact(av.y * rcp);
            av.z = gelu_exact(av.z * rcp); av.w = gelu_exact(av.w * rcp);
        }
        __nv_bfloat16 h0, h1, h2, h3, l0, l1, l2, l3;
        bsplit(av.x, h0, l0); bsplit(av.y, h1, l1);
        bsplit(av.z, h2, l2); bsplit(av.w, h3, l3);
        uint32_t off = (uint32_t)(r * WROW + k) * 2;
        __nv_bfloat162 p;
        p.x = h0; p.y = h1; *(__nv_bfloat162*)(smem + SM_AHI + off) = p;
        p.x = h2; p.y = h3; *(__nv_bfloat162*)(smem + SM_AHI + off + 4) = p;
        p.x = l0; p.y = l1; *(__nv_bfloat162*)(smem + SM_ALO + off) = p;
        p.x = l2; p.y = l3; *(__nv_bfloat162*)(smem + SM_ALO + off + 4) = p;
    }
    asm volatile("cp.async.wait_group 0;" ::: "memory");
    __syncthreads();

    int warpM = wid >> 2;           // 0..3 -> 32 rows
    int warpN = wid & 3;            // 0..3 -> 32 cols
    uint32_t a_lane = sb + SM_AHI +
        ((uint32_t)((warpM * 32 + (lane & 15)) * WROW + ((lane >> 4) << 3)) << 1);
    uint32_t b_lane = sb + SM_WHI +
        ((uint32_t)((warpN * 32 + (lane & 7) + ((lane >> 4) << 3)) * WROW +
                    (((lane >> 3) & 1) << 3)) << 1);

    float acc[2][4][4];
#pragma unroll
    for (int i = 0; i < 2; i++)
#pragma unroll
        for (int j = 0; j < 4; j++)
#pragma unroll
            for (int q = 0; q < 4; q++) acc[i][j][q] = 0.f;

#pragma unroll
    for (int p = 0; p < 3; p++) {
        uint32_t abase = a_lane + (p == 2 ? (uint32_t)WIMG_BYTES : 0u);
        uint32_t bbase = b_lane + (p == 1 ? (uint32_t)WIMG_BYTES : 0u);
#pragma unroll
        for (int ks = 0; ks < 8; ks++) {
            uint32_t ar[2][4], br[2][4];
            ldm_x4(ar[0], abase + ks * 32);
            ldm_x4(ar[1], abase + ks * 32 + 16 * WROW * 2);
            ldm_x4(br[0], bbase + ks * 32);
            ldm_x4(br[1], bbase + ks * 32 + 16 * WROW * 2);
#pragma unroll
            for (int mt = 0; mt < 2; mt++) {
                mma16816(acc[mt][0], ar[mt], br[0] + 0);
                mma16816(acc[mt][1], ar[mt], br[0] + 2);
                mma16816(acc[mt][2], ar[mt], br[1] + 0);
                mma16816(acc[mt][3], ar[mt], br[1] + 2);
            }
        }
    }

    // epilogue
    int gid = lane >> 2, tq = lane & 3;
    float g = 0.f, og = 0.f;
    if (EPI == EPI_GATED) { g = 1.f / (1.f + expf(-*gate_p)); og = 1.f - g; }
#pragma unroll
    for (int mt = 0; mt < 2; mt++) {
#pragma unroll
        for (int nt = 0; nt < 4; nt++) {
            int col = warpN * 32 + nt * 8 + tq * 2;
            float2 bv = *(const float2*)(bias + col);
#pragma unroll
            for (int half = 0; half < 2; half++) {
                int row = row0 + warpM * 32 + mt * 16 + gid + half * 8;
                if (row >= N) continue;
                float c0 = acc[mt][nt][half * 2 + 0] + bv.x;
                float c1 = acc[mt][nt][half * 2 + 1] + bv.y;
                if (EPI == EPI_RELU) { c0 = fmaxf(c0, 0.f); c1 = fmaxf(c1, 0.f); }
                if (EPI == EPI_GATED) {
                    float2 xp = *(const float2*)(xprev + (size_t)row * HC + col);
                    c0 = g * c0 + og * xp.x;
                    c1 = g * c1 + og * xp.y;
                }
                *(float2*)(C + (size_t)row * HC + col) = make_float2(c0, c1);
            }
        }
    }
}

// ---------------- small utility kernels ----------------
__global__ void fill_kernel(float* __restrict__ p, float v, int n) {
    int i = blockIdx.x * blockDim.x + threadIdx.x;
    if (i < n) p[i] = v;
}

// one launch clears amax(-inf), den(0) [Nd*4] and agg(0) [Nd*128]
__global__ void attn_clear_kernel(float* __restrict__ amax, float* __restrict__ den,
                                  float* __restrict__ agg, int nd4, int ndc) {
    int i = blockIdx.x * blockDim.x + threadIdx.x;
    if (i < nd4) { amax[i] = -INFINITY; den[i] = 0.f; }
    if (i < ndc) agg[i] = 0.f;
}

// ---------------- attention kernels ----------------
__device__ __forceinline__ void atomicMaxFloat(float* addr, float value) {
    if (value >= 0.f)
        atomicMax((int*)addr, __float_as_int(value));
    else
        atomicMin((unsigned int*)addr, __float_as_uint(value));
}

__global__ void attn_alpha_kernel(const float* __restrict__ q, const float* __restrict__ kt,
                                  const int* __restrict__ src, const int* __restrict__ dst,
                                  const float* __restrict__ prel,
                                  float* __restrict__ alpha, float* __restrict__ amax, int E) {
    int e = blockIdx.x * 8 + (threadIdx.x >> 5);
    if (e >= E) return;
    int lane = threadIdx.x & 31;
    int s = src[e], d = dst[e];
    float4 qv = *(const float4*)(q + (size_t)d * HC + lane * 4);
    float4 kv = *(const float4*)(kt + (size_t)s * HC + lane * 4);
    float p = qv.x * kv.x + qv.y * kv.y + qv.z * kv.z + qv.w * kv.w;
    p += __shfl_xor_sync(0xffffffffu, p, 1);
    p += __shfl_xor_sync(0xffffffffu, p, 2);
    p += __shfl_xor_sync(0xffffffffu, p, 4);
    if ((lane & 7) == 0) {
        int h = lane >> 3;
        float a = p * prel[h] * 0.17677669529663687f;
        alpha[(size_t)e * 4 + h] = a;
        atomicMaxFloat(&amax[(size_t)d * 4 + h], a);
    }
}

__global__ void attn_exp_kernel(float* __restrict__ alpha, const int* __restrict__ dst,
                                const float* __restrict__ amax, float* __restrict__ den, int E) {
    int t = blockIdx.x * blockDim.x + threadIdx.x;
    if (t >= E * 4) return;
    int e = t >> 2, h = t & 3;
    int d = dst[e];
    float ex = expf(alpha[t] - amax[(size_t)d * 4 + h]);
    alpha[t] = ex;
    atomicAdd(&den[(size_t)d * 4 + h], ex);
}

// unnormalized scatter: agg[dst] += vt[src] * ex (normalization fused into gated GEMM)
__global__ void attn_scatter_kernel(const float* __restrict__ ex, const float* __restrict__ vt,
                                    const int* __restrict__ src, const int* __restrict__ dst,
                                    float* __restrict__ agg, int E) {
    int e = blockIdx.x * 8 + (threadIdx.x >> 5);
    if (e >= E) return;
    int lane = threadIdx.x & 31;
    int s = src[e], d = dst[e];
    int h = lane >> 3;
    float w = ex[(size_t)e * 4 + h];
    float4 vv = *(const float4*)(vt + (size_t)s * HC + lane * 4);
    vv.x *= w; vv.y *= w; vv.z *= w; vv.w *= w;
    atomicAdd((float4*)(agg + (size_t)d * HC + lane * 4), vv);
}

// ---------------- output head ----------------
__global__ void out_head_kernel(const float* __restrict__ X, const float* __restrict__ W2,
                                const float* __restrict__ b2, const int* __restrict__ batch,
                                float* __restrict__ gsum, float* __restrict__ gcnt, int N) {
    int n = blockIdx.x * 8 + (threadIdx.x >> 5);
    if (n >= N) return;
    int lane = threadIdx.x & 31;
    float4 x = *(const float4*)(X + (size_t)n * HC + lane * 4);
    float4 wa = *(const float4*)(W2 + lane * 8);
    float4 wb = *(const float4*)(W2 + lane * 8 + 4);
    float p0 = x.x * wa.x + x.y * wa.z + x.z * wb.x + x.w * wb.z;
    float p1 = x.x * wa.y + x.y * wa.w + x.z * wb.y + x.w * wb.w;
#pragma unroll
    for (int off = 16; off > 0; off >>= 1) {
        p0 += __shfl_xor_sync(0xffffffffu, p0, off);
        p1 += __shfl_xor_sync(0xffffffffu, p1, off);
    }
    if (lane == 0) {
        float l0 = p0 + b2[0], l1 = p1 + b2[1];
        float m = fmaxf(l0, l1);
        float e0 = expf(l0 - m), e1 = expf(l1 - m);
        float inv = 1.f / (e0 + e1);
        int g = batch[n];
        atomicAdd(&gsum[g * 2 + 0], e0 * inv);
        atomicAdd(&gsum[g * 2 + 1], e1 * inv);
        atomicAdd(&gcnt[g], 1.f);
    }
}

__global__ void finalize_kernel(const float* __restrict__ gsum, const float* __restrict__ gcnt,
                                float* __restrict__ out, int G) {
    int g = blockIdx.x * blockDim.x + threadIdx.x;
    if (g >= G) return;
    float c = fmaxf(gcnt[g], 1.f);
    out[g * 2 + 0] = gsum[g * 2 + 0] / c;
    out[g * 2 + 1] = gsum[g * 2 + 1] / c;
}

// ---------------- host orchestration ----------------
static inline void fillf(float* p, float v, int n) {
    fill_kernel<<<(n + 255) / 256, 256>>>(p, v, n);
}

#define IMG(j) (wimg + (size_t)(j) * 2 * WIMG_ELEMS)
#define MMTC(NORM, EPI, A, J, B, C, N, GATE, XP, DEN)                                  \
    mm_mma_kernel<NORM, EPI><<<((N) + 127) / 128, 512, SMEM_MM>>>(A, IMG(J), B, C, N, GATE, XP, DEN)

extern "C" void kernel_launch(void* const* d_in, const int* in_sizes, int n_in,
                              void* d_out, int out_size) {
    const float* x_var = (const float*)d_in[0];
    const float* x_con = (const float*)d_in[1];
    const float* mlp_in_w = (const float*)d_in[2];
    const float* mlp_in_b = (const float*)d_in[3];
    const float* w0 = (const float*)d_in[4];
    const float* b0 = (const float*)d_in[5];
    const float* w1 = (const float*)d_in[6];
    const float* b1 = (const float*)d_in[7];
    const float* w2 = (const float*)d_in[8];
    const float* b2 = (const float*)d_in[9];
    const float* k_w = (const float*)d_in[10];
    const float* k_b = (const float*)d_in[11];
    const float* q_w = (const float*)d_in[12];
    const float* q_b = (const float*)d_in[13];
    const float* v_w = (const float*)d_in[14];
    const float* v_b = (const float*)d_in[15];
    const float* a_w = (const float*)d_in[16];
    const float* a_b = (const float*)d_in[17];
    const float* skip = (const float*)d_in[18];
    const float* a_rel = (const float*)d_in[19];
    const float* m_rel = (const float*)d_in[20];
    const float* p_rel = (const float*)d_in[21];
    const int* evc = (const int*)d_in[22];
    const int* ecv = (const int*)d_in[23];
    const int* batch = (const int*)d_in[24];
    float* out = (float*)d_out;

    int Nv = in_sizes[0] / HC;
    int Nc = in_sizes[1] / HC;
    int Evc = in_sizes[22] / 2;
    int Ecv = in_sizes[23] / 2;

    float *xs0, *xs1, *tmp, *kt, *vt, *qb, *aggv, *aggc, *alpha, *amax, *den0, *den1, *bcomp, *gsum, *gcnt;
    __nv_bfloat16* wimg;
    cudaGetSymbolAddress((void**)&xs0, g_xs0);
    cudaGetSymbolAddress((void**)&xs1, g_xs1);
    cudaGetSymbolAddress((void**)&tmp, g_tmp);
    cudaGetSymbolAddress((void**)&kt, g_kt);
    cudaGetSymbolAddress((void**)&vt, g_vt);
    cudaGetSymbolAddress((void**)&qb, g_q);
    cudaGetSymbolAddress((void**)&aggv, g_aggv);
    cudaGetSymbolAddress((void**)&aggc, g_aggc);
    cudaGetSymbolAddress((void**)&alpha, g_alpha);
    cudaGetSymbolAddress((void**)&amax, g_amax);
    cudaGetSymbolAddress((void**)&den0, g_den0);
    cudaGetSymbolAddress((void**)&den1, g_den1);
    cudaGetSymbolAddress((void**)&wimg, g_wimg);
    cudaGetSymbolAddress((void**)&bcomp, g_bcomp);
    cudaGetSymbolAddress((void**)&gsum, g_gsum);
    cudaGetSymbolAddress((void**)&gcnt, g_gcnt);

    cudaFuncSetAttribute(mm_mma_kernel<false, EPI_NONE>,
                         cudaFuncAttributeMaxDynamicSharedMemorySize, SMEM_MM);
    cudaFuncSetAttribute(mm_mma_kernel<false, EPI_RELU>,
                         cudaFuncAttributeMaxDynamicSharedMemorySize, SMEM_MM);
    cudaFuncSetAttribute(mm_mma_kernel<true, EPI_GATED>,
                         cudaFuncAttributeMaxDynamicSharedMemorySize, SMEM_MM);

    // ---- weight packing jobs ----
    PackJobs pj;
    for (int j = 0; j < NW; j++) { pj.w[j] = nullptr; pj.rel[j] = nullptr; pj.bin[j] = nullptr; pj.bout[j] = nullptr; }
    for (int t = 0; t < 2; t++)
        for (int i = 0; i < 3; i++) pj.w[t * 3 + i] = mlp_in_w + (size_t)(t * 3 + i) * 16384;
    for (int l = 0; l < LAYERS; l++)
        for (int et = 0; et < 2; et++) {
            int li = l * 2 + et;
            pj.w[6 + li] = k_w + (size_t)li * 16384;
            pj.rel[6 + li] = a_rel + (size_t)li * 4096;
            pj.bin[6 + li] = k_b + (size_t)li * 128;
            pj.bout[6 + li] = bcomp + (size_t)li * 128;
            pj.w[10 + li] = v_w + (size_t)li * 16384;
            pj.rel[10 + li] = m_rel + (size_t)li * 4096;
            pj.bin[10 + li] = v_b + (size_t)li * 128;
            pj.bout[10 + li] = bcomp + (size_t)(4 + li) * 128;
            pj.w[14 + li] = q_w + (size_t)li * 16384;
            pj.w[18 + li] = a_w + (size_t)li * 16384;
        }
    pj.w[22] = w0;
    pj.w[23] = w1;
    pack_kernel<<<dim3(NW, 4), 256>>>(pj, wimg);

    // ---- input MLPs ----
    MMTC(false, EPI_RELU, x_var, 0, mlp_in_b + 0 * 128, xs0, Nv, nullptr, nullptr, nullptr);
    MMTC(false, EPI_RELU, xs0,   1, mlp_in_b + 1 * 128, xs0, Nv, nullptr, nullptr, nullptr);
    MMTC(false, EPI_NONE, xs0,   2, mlp_in_b + 2 * 128, xs0, Nv, nullptr, nullptr, nullptr);
    MMTC(false, EPI_RELU, x_con, 3, mlp_in_b + 3 * 128, xs1, Nc, nullptr, nullptr, nullptr);
    MMTC(false, EPI_RELU, xs1,   4, mlp_in_b + 4 * 128, xs1, Nc, nullptr, nullptr, nullptr);
    MMTC(false, EPI_NONE, xs1,   5, mlp_in_b + 5 * 128, xs1, Nc, nullptr, nullptr, nullptr);

    // ---- HGTConv layers ----
    for (int l = 0; l < LAYERS; l++) {
        for (int et = 0; et < 2; et++) {
            int st = et, dt = 1 - et;
            const float* xs_s = (st == 0) ? xs0 : xs1;
            const float* xs_d = (dt == 0) ? xs0 : xs1;
            int Ns = (st == 0) ? Nv : Nc;
            int Nd = (dt == 0) ? Nv : Nc;
            const int* edges = (et == 0) ? evc : ecv;
            int E = (et == 0) ? Evc : Ecv;
            const int* esrc = edges;
            const int* edst = edges + E;
            float* agg = (dt == 0) ? aggv : aggc;
            float* den = (dt == 0) ? den0 : den1;
            int li = l * 2 + et;

            MMTC(false, EPI_NONE, xs_s, 6 + li, bcomp + (size_t)li * 128, kt, Ns, nullptr, nullptr, nullptr);
            MMTC(false, EPI_NONE, xs_s, 10 + li, bcomp + (size_t)(4 + li) * 128, vt, Ns, nullptr, nullptr, nullptr);
            MMTC(false, EPI_NONE, xs_d, 14 + l * 2 + dt, q_b + (size_t)(l * 2 + dt) * 128, qb, Nd, nullptr, nullptr, nullptr);

            attn_clear_kernel<<<(Nd * HC + 255) / 256, 256>>>(amax, den, agg, Nd * 4, Nd * HC);
            attn_alpha_kernel<<<(E + 7) / 8, 256>>>(qb, kt, esrc, edst,
                                                    p_rel + (size_t)li * 4, alpha, amax, E);
            attn_exp_kernel<<<(E * 4 + 255) / 256, 256>>>(alpha, edst, amax, den, E);
            attn_scatter_kernel<<<(E + 7) / 8, 256>>>(alpha, vt, esrc, edst, agg, E);
        }
        MMTC(true, EPI_GATED, aggv, 18 + l * 2 + 0, a_b + (size_t)(l * 2 + 0) * 128,
             xs0, Nv, skip + l * 2 + 0, xs0, den0);
        MMTC(true, EPI_GATED, aggc, 18 + l * 2 + 1, a_b + (size_t)(l * 2 + 1) * 128,
             xs1, Nc, skip + l * 2 + 1, xs1, den1);
    }

    // ---- output head ----
    MMTC(false, EPI_RELU, xs0, 22, b0, tmp, Nv, nullptr, nullptr, nullptr);
    MMTC(false, EPI_RELU, tmp, 23, b1, tmp, Nv, nullptr, nullptr, nullptr);
    fillf(gsum, 0.f, NG * 2);
    fillf(gcnt, 0.f, NG);
    out_head_kernel<<<(Nv + 7) / 8, 256>>>(tmp, w2, b2, batch, gsum, gcnt, Nv);
    finalize_kernel<<<(NG + 255) / 256, 256>>>(gsum, gcnt, out, NG);
}